// round 12
// baseline (speedup 1.0000x reference)
#include <cuda_runtime.h>
#include <cuda_bf16.h>
#include <math.h>

#define N_BINS 20
#define FULL_MASK 0xFFFFFFFFu

// Global scratch. Zero at module load; last block resets after finalizing, so
// every complete kernel_launch leaves them zeroed (graph-replay deterministic).
__device__ double       g_conf_sum[N_BINS];
__device__ unsigned int g_cnt[N_BINS];
__device__ unsigned int g_acc[N_BINS];
__device__ unsigned int g_done;

// Row reduce: value-max via fmaxf tree (FMNMX, fma pipe) + REDUX on the bit
// pattern (positive floats are uint-order-monotone), then first-occurrence
// argmax recovered post-hoc via equality mask + ballot + ffs.
__device__ __forceinline__ void reduce_row(float4 v, int lane,
                                           float& conf, int& idx) {
    float m = fmaxf(fmaxf(v.x, v.y), fmaxf(v.z, v.w));
    unsigned int wmax = __reduce_max_sync(FULL_MASK, __float_as_uint(m));
    unsigned int e = (__float_as_uint(v.x) == wmax ? 1u : 0u)
                   | (__float_as_uint(v.y) == wmax ? 2u : 0u)
                   | (__float_as_uint(v.z) == wmax ? 4u : 0u)
                   | (__float_as_uint(v.w) == wmax ? 8u : 0u);
    unsigned int bal = __ballot_sync(FULL_MASK, e != 0u);
    int wlane = __ffs(bal) - 1;                  // lowest lane -> first occurrence
    int lidx  = (lane << 2) + __ffs(e) - 1;      // valid where e != 0
    idx  = __shfl_sync(FULL_MASK, lidx, wlane);
    conf = __uint_as_float(wmax);
}

__global__ __launch_bounds__(256) void ece_main_kernel(
    const float4* __restrict__ softmaxes,  // [N, 32] float4 view of [N,128]
    const int*    __restrict__ labels,
    float*        __restrict__ out,        // [21]: ece, ys[20]
    int n)
{
    __shared__ float        s_conf[N_BINS];
    __shared__ unsigned int s_cntacc[N_BINS];   // cnt in [0:16), correct in [16:32)
    __shared__ unsigned int s_dummy[N_BINS];    // atomic-completion sink
    __shared__ unsigned int s_is_last;

    int t = threadIdx.x;
    if (t < N_BINS) { s_conf[t] = 0.0f; s_cntacc[t] = 0u; }
    __syncthreads();

    int lane   = t & 31;
    unsigned int gwarp  = (blockIdx.x * blockDim.x + t) >> 5;
    unsigned int nwarps = (gridDim.x * blockDim.x) >> 5;

    int ngroups = n >> 2;                       // groups of 4 rows

    for (unsigned int g = gwarp; g < (unsigned int)ngroups; g += nwarps) {
        unsigned int base = g * 128u + (unsigned int)lane;
        // 4 independent loads -> MLP=4 (32-bit indexing; 32M float4 < 2^31)
        float4 v0 = softmaxes[base];
        float4 v1 = softmaxes[base + 32u];
        float4 v2 = softmaxes[base + 64u];
        float4 v3 = softmaxes[base + 96u];
        int4 lab = ((const int4*)labels)[g];    // uniform across warp

        float c0, c1, c2, c3; int x0, x1, x2, x3;
        reduce_row(v0, lane, c0, x0);
        reduce_row(v1, lane, c1, x1);
        reduce_row(v2, lane, c2, x2);
        reduce_row(v3, lane, c3, x3);

        // lanes 0..3 each commit one row (all lanes hold all 4 results)
        if (lane < 4) {
            float conf; int idx; int label;
            if      (lane == 0) { conf = c0; idx = x0; label = lab.x; }
            else if (lane == 1) { conf = c1; idx = x1; label = lab.y; }
            else if (lane == 2) { conf = c2; idx = x2; label = lab.z; }
            else                { conf = c3; idx = x3; label = lab.w; }

            int b = (int)ceilf(conf * (float)N_BINS) - 1;
            b = min(max(b, 0), N_BINS - 1);
            unsigned int correct = (idx == label) ? 1u : 0u;
            atomicAdd(&s_conf[b], conf);
            atomicAdd(&s_cntacc[b], 1u | (correct << 16));
        }
    }

    // tail rows (n not divisible by 4): warp 0
    if (gwarp == 0) {
        for (int row = ngroups << 2; row < n; row++) {
            float4 v = softmaxes[(unsigned int)row * 32u + (unsigned int)lane];
            float cf; int xi;
            reduce_row(v, lane, cf, xi);
            if (lane == 0) {
                int b = (int)ceilf(cf * (float)N_BINS) - 1;
                b = min(max(b, 0), N_BINS - 1);
                unsigned int correct = (xi == labels[row]) ? 1u : 0u;
                atomicAdd(&s_conf[b], cf);
                atomicAdd(&s_cntacc[b], 1u | (correct << 16));
            }
        }
    }

    // ── flush block partials (no __threadfence: consumed atomic returns +
    //    dependent STS + BAR.SYNC STS-drain order the flush before g_done).
    __syncthreads();
    if (t < N_BINS) {
        unsigned int ca = s_cntacc[t];
        unsigned int sink = 0u;
        if (ca) {
            double od = atomicAdd(&g_conf_sum[t], (double)s_conf[t]);
            unsigned int o1 = atomicAdd(&g_cnt[t], ca & 0xFFFFu);
            unsigned int o2 = atomicAdd(&g_acc[t], ca >> 16);
            sink = o1 ^ o2 ^ (unsigned int)__double2loint(od);
        }
        s_dummy[t] = sink;          // dependent STS: waits on atomic results
    }
    __syncthreads();                // drains pending STS (and thus the atomics)

    if (t == 0) {
        unsigned int prev = atomicAdd(&g_done, 1u);
        s_is_last = (prev == gridDim.x - 1) ? 1u : 0u;
    }
    __syncthreads();

    // last-block finalize: reads via L2 (__ldcg) — all flushes are performed
    if (s_is_last && t < 32) {
        int b = t;
        float contrib = 0.0f;
        if (b < N_BINS) {
            unsigned int c = __ldcg(&g_cnt[b]);
            float y = 0.0f;
            if (c) {
                double cs      = __ldcg(&g_conf_sum[b]);
                unsigned int a = __ldcg(&g_acc[b]);
                float avg_conf = (float)(cs / (double)c);
                float avg_acc  = (float)a / (float)c;
                float prop     = (float)c / (float)n;
                contrib = fabsf(avg_conf - avg_acc) * prop;
                y = avg_acc;
            }
            out[1 + b] = y;
            // reset for next (graph-replayed) launch
            g_conf_sum[b] = 0.0;
            g_cnt[b] = 0u;
            g_acc[b] = 0u;
        }
        #pragma unroll
        for (int off = 16; off > 0; off >>= 1)
            contrib += __shfl_down_sync(FULL_MASK, contrib, off);
        if (b == 0) {
            out[0] = contrib;
            g_done = 0u;
        }
    }
}

extern "C" void kernel_launch(void* const* d_in, const int* in_sizes, int n_in,
                              void* d_out, int out_size) {
    const float* softmaxes = (const float*)d_in[0];
    const int*   labels    = (const int*)d_in[1];
    float*       out       = (float*)d_out;

    int n = in_sizes[1];              // number of rows = label count
    (void)n_in; (void)out_size;

    int threads = 256;
    int blocks  = 1216;               // one full wave on 152 SMs (best measured)
    ece_main_kernel<<<blocks, threads>>>((const float4*)softmaxes, labels, out, n);
}

// round 13
// speedup vs baseline: 1.1678x; 1.1678x over previous
#include <cuda_runtime.h>
#include <cuda_bf16.h>
#include <math.h>

#define N_BINS 20
#define FULL_MASK 0xFFFFFFFFu

// Global scratch. Zero at module load; last block resets after finalizing, so
// every complete kernel_launch leaves them zeroed (graph-replay deterministic).
__device__ double       g_conf_sum[N_BINS];
__device__ unsigned int g_cnt[N_BINS];
__device__ unsigned int g_acc[N_BINS];
__device__ unsigned int g_done;

// Row reduce: value-max via fmaxf tree (FMNMX, fma pipe) + REDUX on the bit
// pattern (positive floats are uint-order-monotone), then first-occurrence
// argmax recovered post-hoc via equality mask + ballot + ffs.
__device__ __forceinline__ void reduce_row(float4 v, int lane,
                                           float& conf, int& idx) {
    float m = fmaxf(fmaxf(v.x, v.y), fmaxf(v.z, v.w));
    unsigned int wmax = __reduce_max_sync(FULL_MASK, __float_as_uint(m));
    unsigned int e = (__float_as_uint(v.x) == wmax ? 1u : 0u)
                   | (__float_as_uint(v.y) == wmax ? 2u : 0u)
                   | (__float_as_uint(v.z) == wmax ? 4u : 0u)
                   | (__float_as_uint(v.w) == wmax ? 8u : 0u);
    unsigned int bal = __ballot_sync(FULL_MASK, e != 0u);
    int wlane = __ffs(bal) - 1;                  // lowest lane -> first occurrence
    int lidx  = (lane << 2) + __ffs(e) - 1;      // valid where e != 0
    idx  = __shfl_sync(FULL_MASK, lidx, wlane);
    conf = __uint_as_float(wmax);
}

__global__ __launch_bounds__(256) void ece_main_kernel(
    const float4* __restrict__ softmaxes,  // [N, 32] float4 view of [N,128]
    const int*    __restrict__ labels,
    float*        __restrict__ out,        // [21]: ece, ys[20]
    int n)
{
    __shared__ float        s_conf[N_BINS];
    __shared__ unsigned int s_cntacc[N_BINS];   // cnt in [0:16), correct in [16:32)
    __shared__ unsigned int s_dummy[N_BINS];    // atomic-completion sink
    __shared__ unsigned int s_is_last;

    int t = threadIdx.x;
    if (t < N_BINS) { s_conf[t] = 0.0f; s_cntacc[t] = 0u; }
    __syncthreads();

    int lane   = t & 31;
    unsigned int gwarp  = (blockIdx.x * blockDim.x + t) >> 5;
    unsigned int nwarps = (gridDim.x * blockDim.x) >> 5;

    int ngroups = n >> 2;                       // groups of 4 rows

    for (unsigned int g = gwarp; g < (unsigned int)ngroups; g += nwarps) {
        unsigned int base = g * 128u + (unsigned int)lane;
        // 4 independent loads -> MLP=4 (32-bit indexing; 32M float4 < 2^31)
        float4 v0 = softmaxes[base];
        float4 v1 = softmaxes[base + 32u];
        float4 v2 = softmaxes[base + 64u];
        float4 v3 = softmaxes[base + 96u];
        int4 lab = ((const int4*)labels)[g];    // uniform across warp

        float c0, c1, c2, c3; int x0, x1, x2, x3;
        reduce_row(v0, lane, c0, x0);
        reduce_row(v1, lane, c1, x1);
        reduce_row(v2, lane, c2, x2);
        reduce_row(v3, lane, c3, x3);

        // lanes 0..3 each commit one row (all lanes hold all 4 results)
        if (lane < 4) {
            float conf; int idx; int label;
            if      (lane == 0) { conf = c0; idx = x0; label = lab.x; }
            else if (lane == 1) { conf = c1; idx = x1; label = lab.y; }
            else if (lane == 2) { conf = c2; idx = x2; label = lab.z; }
            else                { conf = c3; idx = x3; label = lab.w; }

            int b = (int)ceilf(conf * (float)N_BINS) - 1;
            b = min(max(b, 0), N_BINS - 1);
            unsigned int correct = (idx == label) ? 1u : 0u;
            atomicAdd(&s_conf[b], conf);
            atomicAdd(&s_cntacc[b], 1u | (correct << 16));
        }
    }

    // tail rows (n not divisible by 4): warp 0
    if (gwarp == 0) {
        for (int row = ngroups << 2; row < n; row++) {
            float4 v = softmaxes[(unsigned int)row * 32u + (unsigned int)lane];
            float cf; int xi;
            reduce_row(v, lane, cf, xi);
            if (lane == 0) {
                int b = (int)ceilf(cf * (float)N_BINS) - 1;
                b = min(max(b, 0), N_BINS - 1);
                unsigned int correct = (xi == labels[row]) ? 1u : 0u;
                atomicAdd(&s_conf[b], cf);
                atomicAdd(&s_cntacc[b], 1u | (correct << 16));
            }
        }
    }

    // ── flush block partials (no __threadfence: consumed atomic returns +
    //    dependent STS + BAR.SYNC STS-drain order the flush before g_done).
    __syncthreads();
    if (t < N_BINS) {
        unsigned int ca = s_cntacc[t];
        unsigned int sink = 0u;
        if (ca) {
            double od = atomicAdd(&g_conf_sum[t], (double)s_conf[t]);
            unsigned int o1 = atomicAdd(&g_cnt[t], ca & 0xFFFFu);
            unsigned int o2 = atomicAdd(&g_acc[t], ca >> 16);
            sink = o1 ^ o2 ^ (unsigned int)__double2loint(od);
        }
        s_dummy[t] = sink;          // dependent STS: waits on atomic results
    }
    __syncthreads();                // drains pending STS (and thus the atomics)

    if (t == 0) {
        unsigned int prev = atomicAdd(&g_done, 1u);
        s_is_last = (prev == gridDim.x - 1) ? 1u : 0u;
    }
    __syncthreads();

    // last-block finalize: reads via L2 (__ldcg) — all flushes are performed
    if (s_is_last && t < 32) {
        int b = t;
        float contrib = 0.0f;
        if (b < N_BINS) {
            unsigned int c = __ldcg(&g_cnt[b]);
            float y = 0.0f;
            if (c) {
                double cs      = __ldcg(&g_conf_sum[b]);
                unsigned int a = __ldcg(&g_acc[b]);
                float avg_conf = (float)(cs / (double)c);
                float avg_acc  = (float)a / (float)c;
                float prop     = (float)c / (float)n;
                contrib = fabsf(avg_conf - avg_acc) * prop;
                y = avg_acc;
            }
            out[1 + b] = y;
            // reset for next (graph-replayed) launch
            g_conf_sum[b] = 0.0;
            g_cnt[b] = 0u;
            g_acc[b] = 0u;
        }
        #pragma unroll
        for (int off = 16; off > 0; off >>= 1)
            contrib += __shfl_down_sync(FULL_MASK, contrib, off);
        if (b == 0) {
            out[0] = contrib;
            g_done = 0u;
        }
    }
}

extern "C" void kernel_launch(void* const* d_in, const int* in_sizes, int n_in,
                              void* d_out, int out_size) {
    const float* softmaxes = (const float*)d_in[0];
    const int*   labels    = (const int*)d_in[1];
    float*       out       = (float*)d_out;

    int n = in_sizes[1];              // number of rows = label count
    (void)n_in; (void)out_size;

    int threads = 256;
    int blocks  = 1216;               // one full wave on 152 SMs (best measured)
    ece_main_kernel<<<blocks, threads>>>((const float4*)softmaxes, labels, out, n);
}

// round 14
// speedup vs baseline: 1.1811x; 1.0114x over previous
#include <cuda_runtime.h>
#include <cuda_bf16.h>
#include <math.h>

#define N_BINS 20
#define FULL_MASK 0xFFFFFFFFu

// Global scratch. Zero at module load; last block resets after finalizing, so
// every complete kernel_launch leaves them zeroed (graph-replay deterministic).
__device__ double       g_conf_sum[N_BINS];
__device__ unsigned int g_cnt[N_BINS];
__device__ unsigned int g_acc[N_BINS];
__device__ unsigned int g_done;

// Row reduce: value-max via fmaxf tree (FMNMX, fma pipe) + REDUX on the bit
// pattern (positive floats are uint-order-monotone), then first-occurrence
// argmax recovered post-hoc via equality mask + ballot + ffs.
__device__ __forceinline__ void reduce_row(float4 v, int lane,
                                           float& conf, int& idx) {
    float m = fmaxf(fmaxf(v.x, v.y), fmaxf(v.z, v.w));
    unsigned int wmax = __reduce_max_sync(FULL_MASK, __float_as_uint(m));
    unsigned int e = (__float_as_uint(v.x) == wmax ? 1u : 0u)
                   | (__float_as_uint(v.y) == wmax ? 2u : 0u)
                   | (__float_as_uint(v.z) == wmax ? 4u : 0u)
                   | (__float_as_uint(v.w) == wmax ? 8u : 0u);
    unsigned int bal = __ballot_sync(FULL_MASK, e != 0u);
    int wlane = __ffs(bal) - 1;                  // lowest lane -> first occurrence
    int lidx  = (lane << 2) + __ffs(e) - 1;      // valid where e != 0
    idx  = __shfl_sync(FULL_MASK, lidx, wlane);
    conf = __uint_as_float(wmax);
}

__global__ __launch_bounds__(256) void ece_main_kernel(
    const float4* __restrict__ softmaxes,  // [N, 32] float4 view of [N,128]
    const int*    __restrict__ labels,
    float*        __restrict__ out,        // [21]: ece, ys[20]
    int n)
{
    __shared__ float        s_conf[N_BINS];
    __shared__ unsigned int s_cntacc[N_BINS];   // cnt in [0:16), correct in [16:32)
    __shared__ unsigned int s_dummy[N_BINS];    // atomic-completion sink
    __shared__ unsigned int s_is_last;

    int t = threadIdx.x;
    if (t < N_BINS) { s_conf[t] = 0.0f; s_cntacc[t] = 0u; }
    __syncthreads();

    int lane   = t & 31;
    unsigned int gwarp  = (blockIdx.x * blockDim.x + t) >> 5;
    unsigned int nwarps = (gridDim.x * blockDim.x) >> 5;

    int ngroups = n >> 2;                       // groups of 4 rows

    for (unsigned int g = gwarp; g < (unsigned int)ngroups; g += nwarps) {
        unsigned int base = g * 128u + (unsigned int)lane;
        // 4 independent loads -> MLP=4 (32-bit indexing; 32M float4 < 2^31)
        float4 v0 = softmaxes[base];
        float4 v1 = softmaxes[base + 32u];
        float4 v2 = softmaxes[base + 64u];
        float4 v3 = softmaxes[base + 96u];
        int4 lab = ((const int4*)labels)[g];    // uniform across warp

        float c0, c1, c2, c3; int x0, x1, x2, x3;
        reduce_row(v0, lane, c0, x0);
        reduce_row(v1, lane, c1, x1);
        reduce_row(v2, lane, c2, x2);
        reduce_row(v3, lane, c3, x3);

        // lanes 0..3 each commit one row (all lanes hold all 4 results)
        if (lane < 4) {
            float conf; int idx; int label;
            if      (lane == 0) { conf = c0; idx = x0; label = lab.x; }
            else if (lane == 1) { conf = c1; idx = x1; label = lab.y; }
            else if (lane == 2) { conf = c2; idx = x2; label = lab.z; }
            else                { conf = c3; idx = x3; label = lab.w; }

            int b = (int)ceilf(conf * (float)N_BINS) - 1;
            b = min(max(b, 0), N_BINS - 1);
            unsigned int correct = (idx == label) ? 1u : 0u;
            atomicAdd(&s_conf[b], conf);
            atomicAdd(&s_cntacc[b], 1u | (correct << 16));
        }
    }

    // tail rows (n not divisible by 4): warp 0
    if (gwarp == 0) {
        for (int row = ngroups << 2; row < n; row++) {
            float4 v = softmaxes[(unsigned int)row * 32u + (unsigned int)lane];
            float cf; int xi;
            reduce_row(v, lane, cf, xi);
            if (lane == 0) {
                int b = (int)ceilf(cf * (float)N_BINS) - 1;
                b = min(max(b, 0), N_BINS - 1);
                unsigned int correct = (xi == labels[row]) ? 1u : 0u;
                atomicAdd(&s_conf[b], cf);
                atomicAdd(&s_cntacc[b], 1u | (correct << 16));
            }
        }
    }

    // ── flush block partials (no __threadfence: consumed atomic returns +
    //    dependent STS + BAR.SYNC STS-drain order the flush before g_done).
    __syncthreads();
    if (t < N_BINS) {
        unsigned int ca = s_cntacc[t];
        unsigned int sink = 0u;
        if (ca) {
            double od = atomicAdd(&g_conf_sum[t], (double)s_conf[t]);
            unsigned int o1 = atomicAdd(&g_cnt[t], ca & 0xFFFFu);
            unsigned int o2 = atomicAdd(&g_acc[t], ca >> 16);
            sink = o1 ^ o2 ^ (unsigned int)__double2loint(od);
        }
        s_dummy[t] = sink;          // dependent STS: waits on atomic results
    }
    __syncthreads();                // drains pending STS (and thus the atomics)

    if (t == 0) {
        unsigned int prev = atomicAdd(&g_done, 1u);
        s_is_last = (prev == gridDim.x - 1) ? 1u : 0u;
    }
    __syncthreads();

    // last-block finalize: reads via L2 (__ldcg) — all flushes are performed
    if (s_is_last && t < 32) {
        int b = t;
        float contrib = 0.0f;
        if (b < N_BINS) {
            unsigned int c = __ldcg(&g_cnt[b]);
            float y = 0.0f;
            if (c) {
                double cs      = __ldcg(&g_conf_sum[b]);
                unsigned int a = __ldcg(&g_acc[b]);
                float avg_conf = (float)(cs / (double)c);
                float avg_acc  = (float)a / (float)c;
                float prop     = (float)c / (float)n;
                contrib = fabsf(avg_conf - avg_acc) * prop;
                y = avg_acc;
            }
            out[1 + b] = y;
            // reset for next (graph-replayed) launch
            g_conf_sum[b] = 0.0;
            g_cnt[b] = 0u;
            g_acc[b] = 0u;
        }
        #pragma unroll
        for (int off = 16; off > 0; off >>= 1)
            contrib += __shfl_down_sync(FULL_MASK, contrib, off);
        if (b == 0) {
            out[0] = contrib;
            g_done = 0u;
        }
    }
}

extern "C" void kernel_launch(void* const* d_in, const int* in_sizes, int n_in,
                              void* d_out, int out_size) {
    const float* softmaxes = (const float*)d_in[0];
    const int*   labels    = (const int*)d_in[1];
    float*       out       = (float*)d_out;

    int n = in_sizes[1];              // number of rows = label count
    (void)n_in; (void)out_size;

    int threads = 256;
    int blocks  = 1216;               // one full wave on 152 SMs (best measured)
    ece_main_kernel<<<blocks, threads>>>((const float4*)softmaxes, labels, out, n);
}

// round 15
// speedup vs baseline: 1.1855x; 1.0037x over previous
#include <cuda_runtime.h>
#include <cuda_bf16.h>
#include <math.h>

#define N_BINS 20
#define FULL_MASK 0xFFFFFFFFu

// Global scratch. Zero at module load; last block resets after finalizing, so
// every complete kernel_launch leaves them zeroed (graph-replay deterministic).
__device__ double       g_conf_sum[N_BINS];
__device__ unsigned int g_cnt[N_BINS];
__device__ unsigned int g_acc[N_BINS];
__device__ unsigned int g_done;

// Row reduce: value-max via fmaxf tree (FMNMX, fma pipe) + REDUX on the bit
// pattern (positive floats are uint-order-monotone), then first-occurrence
// argmax recovered post-hoc via equality mask + ballot + ffs.
__device__ __forceinline__ void reduce_row(float4 v, int lane,
                                           float& conf, int& idx) {
    float m = fmaxf(fmaxf(v.x, v.y), fmaxf(v.z, v.w));
    unsigned int wmax = __reduce_max_sync(FULL_MASK, __float_as_uint(m));
    unsigned int e = (__float_as_uint(v.x) == wmax ? 1u : 0u)
                   | (__float_as_uint(v.y) == wmax ? 2u : 0u)
                   | (__float_as_uint(v.z) == wmax ? 4u : 0u)
                   | (__float_as_uint(v.w) == wmax ? 8u : 0u);
    unsigned int bal = __ballot_sync(FULL_MASK, e != 0u);
    int wlane = __ffs(bal) - 1;                  // lowest lane -> first occurrence
    int lidx  = (lane << 2) + __ffs(e) - 1;      // valid where e != 0
    idx  = __shfl_sync(FULL_MASK, lidx, wlane);
    conf = __uint_as_float(wmax);
}

__global__ __launch_bounds__(256) void ece_main_kernel(
    const float4* __restrict__ softmaxes,  // [N, 32] float4 view of [N,128]
    const int*    __restrict__ labels,
    float*        __restrict__ out,        // [21]: ece, ys[20]
    int n)
{
    __shared__ float        s_conf[N_BINS];
    __shared__ unsigned int s_cntacc[N_BINS];   // cnt in [0:16), correct in [16:32)
    __shared__ unsigned int s_dummy[N_BINS];    // atomic-completion sink
    __shared__ unsigned int s_is_last;

    int t = threadIdx.x;
    if (t < N_BINS) { s_conf[t] = 0.0f; s_cntacc[t] = 0u; }
    __syncthreads();

    int lane   = t & 31;
    unsigned int gwarp  = (blockIdx.x * blockDim.x + t) >> 5;
    unsigned int nwarps = (gridDim.x * blockDim.x) >> 5;

    int ngroups = n >> 2;                       // groups of 4 rows

    for (unsigned int g = gwarp; g < (unsigned int)ngroups; g += nwarps) {
        unsigned int base = g * 128u + (unsigned int)lane;
        // 4 independent loads -> MLP=4 (32-bit indexing; 32M float4 < 2^31)
        float4 v0 = softmaxes[base];
        float4 v1 = softmaxes[base + 32u];
        float4 v2 = softmaxes[base + 64u];
        float4 v3 = softmaxes[base + 96u];
        int4 lab = ((const int4*)labels)[g];    // uniform across warp

        float c0, c1, c2, c3; int x0, x1, x2, x3;
        reduce_row(v0, lane, c0, x0);
        reduce_row(v1, lane, c1, x1);
        reduce_row(v2, lane, c2, x2);
        reduce_row(v3, lane, c3, x3);

        // lanes 0..3 each commit one row (all lanes hold all 4 results)
        if (lane < 4) {
            float conf; int idx; int label;
            if      (lane == 0) { conf = c0; idx = x0; label = lab.x; }
            else if (lane == 1) { conf = c1; idx = x1; label = lab.y; }
            else if (lane == 2) { conf = c2; idx = x2; label = lab.z; }
            else                { conf = c3; idx = x3; label = lab.w; }

            int b = (int)ceilf(conf * (float)N_BINS) - 1;
            b = min(max(b, 0), N_BINS - 1);
            unsigned int correct = (idx == label) ? 1u : 0u;
            atomicAdd(&s_conf[b], conf);
            atomicAdd(&s_cntacc[b], 1u | (correct << 16));
        }
    }

    // tail rows (n not divisible by 4): warp 0
    if (gwarp == 0) {
        for (int row = ngroups << 2; row < n; row++) {
            float4 v = softmaxes[(unsigned int)row * 32u + (unsigned int)lane];
            float cf; int xi;
            reduce_row(v, lane, cf, xi);
            if (lane == 0) {
                int b = (int)ceilf(cf * (float)N_BINS) - 1;
                b = min(max(b, 0), N_BINS - 1);
                unsigned int correct = (xi == labels[row]) ? 1u : 0u;
                atomicAdd(&s_conf[b], cf);
                atomicAdd(&s_cntacc[b], 1u | (correct << 16));
            }
        }
    }

    // ── flush block partials (no __threadfence: consumed atomic returns +
    //    dependent STS + BAR.SYNC STS-drain order the flush before g_done).
    __syncthreads();
    if (t < N_BINS) {
        unsigned int ca = s_cntacc[t];
        unsigned int sink = 0u;
        if (ca) {
            double od = atomicAdd(&g_conf_sum[t], (double)s_conf[t]);
            unsigned int o1 = atomicAdd(&g_cnt[t], ca & 0xFFFFu);
            unsigned int o2 = atomicAdd(&g_acc[t], ca >> 16);
            sink = o1 ^ o2 ^ (unsigned int)__double2loint(od);
        }
        s_dummy[t] = sink;          // dependent STS: waits on atomic results
    }
    __syncthreads();                // drains pending STS (and thus the atomics)

    if (t == 0) {
        unsigned int prev = atomicAdd(&g_done, 1u);
        s_is_last = (prev == gridDim.x - 1) ? 1u : 0u;
    }
    __syncthreads();

    // last-block finalize: reads via L2 (__ldcg) — all flushes are performed
    if (s_is_last && t < 32) {
        int b = t;
        float contrib = 0.0f;
        if (b < N_BINS) {
            unsigned int c = __ldcg(&g_cnt[b]);
            float y = 0.0f;
            if (c) {
                double cs      = __ldcg(&g_conf_sum[b]);
                unsigned int a = __ldcg(&g_acc[b]);
                float avg_conf = (float)(cs / (double)c);
                float avg_acc  = (float)a / (float)c;
                float prop     = (float)c / (float)n;
                contrib = fabsf(avg_conf - avg_acc) * prop;
                y = avg_acc;
            }
            out[1 + b] = y;
            // reset for next (graph-replayed) launch
            g_conf_sum[b] = 0.0;
            g_cnt[b] = 0u;
            g_acc[b] = 0u;
        }
        #pragma unroll
        for (int off = 16; off > 0; off >>= 1)
            contrib += __shfl_down_sync(FULL_MASK, contrib, off);
        if (b == 0) {
            out[0] = contrib;
            g_done = 0u;
        }
    }
}

extern "C" void kernel_launch(void* const* d_in, const int* in_sizes, int n_in,
                              void* d_out, int out_size) {
    const float* softmaxes = (const float*)d_in[0];
    const int*   labels    = (const int*)d_in[1];
    float*       out       = (float*)d_out;

    int n = in_sizes[1];              // number of rows = label count
    (void)n_in; (void)out_size;

    int threads = 256;
    int blocks  = 1216;               // one full wave on 152 SMs (best measured)
    ece_main_kernel<<<blocks, threads>>>((const float4*)softmaxes, labels, out, n);
}